// round 1
// baseline (speedup 1.0000x reference)
#include <cuda_runtime.h>
#include <cstdint>

#define NODES_MAX 100000
#define FDIM 64

// Scratch (allocation-free rule: __device__ globals)
__device__ float g_dinv[NODES_MAX];                // deg -> rsqrt(deg)
__device__ float g_xw [NODES_MAX * FDIM];          // x @ W buffer
__device__ float g_agg[NODES_MAX * FDIM];          // scatter accumulator

// ---------------------------------------------------------------------------
// Degree: deg[i] = 1 (self loop) + count(dst == i); then dinv = rsqrt(deg)
// ---------------------------------------------------------------------------
__global__ void k_deg_init(float* deg, int n) {
    int i = blockIdx.x * blockDim.x + threadIdx.x;
    if (i < n) deg[i] = 1.0f;
}

__global__ void k_deg_count(const int* __restrict__ dst, float* deg, int E) {
    int e = blockIdx.x * blockDim.x + threadIdx.x;
    if (e < E) atomicAdd(&deg[dst[e]], 1.0f);
}

__global__ void k_deg_rsqrt(float* deg, int n) {
    int i = blockIdx.x * blockDim.x + threadIdx.x;
    if (i < n) deg[i] = rsqrtf(deg[i]);
}

// ---------------------------------------------------------------------------
// GEMM: out[n,64] = f(in)[n,64] @ W[64,64]
//   PRE=true: f(v_k) = relu(v_k + bin_k)   (fused bias+ReLU of previous layer)
// blockDim = (64, 4): 4 rows per block, 64 output cols per row.
// ---------------------------------------------------------------------------
template<bool PRE>
__global__ void k_gemm64(const float* __restrict__ in, const float* __restrict__ W,
                         const float* __restrict__ bin, float* __restrict__ out, int n) {
    __shared__ float Ws[FDIM * FDIM];
    __shared__ float rb[4][FDIM];
    const int tx = threadIdx.x;        // 0..63 output col
    const int ty = threadIdx.y;        // 0..3 row in block
    const int tid = ty * 64 + tx;

    #pragma unroll
    for (int i = tid; i < FDIM * FDIM; i += 256) Ws[i] = W[i];

    const int row = blockIdx.x * 4 + ty;
    if (row < n) {
        float v = in[row * FDIM + tx];
        if (PRE) v = fmaxf(v + bin[tx], 0.0f);
        rb[ty][tx] = v;
    }
    __syncthreads();

    if (row < n) {
        float acc = 0.0f;
        #pragma unroll
        for (int k = 0; k < FDIM; k++)
            acc = fmaf(rb[ty][k], Ws[k * FDIM + tx], acc);
        out[row * FDIM + tx] = acc;
    }
}

// ---------------------------------------------------------------------------
// Self-loop init: agg[i,:] = xw[i,:] * dinv[i]^2   (avoids zero-fill + atomics)
// float4 vectorized: n*16 float4 elements.
// ---------------------------------------------------------------------------
__global__ void k_self_init(const float4* __restrict__ xw, float4* __restrict__ agg,
                            const float* __restrict__ dinv, int n16) {
    int i = blockIdx.x * blockDim.x + threadIdx.x;
    if (i >= n16) return;
    float s = dinv[i >> 4];
    float nm = s * s;
    float4 v = xw[i];
    v.x *= nm; v.y *= nm; v.z *= nm; v.w *= nm;
    agg[i] = v;
}

// ---------------------------------------------------------------------------
// Edge scatter: agg[dst,:] += xw[src,:] * dinv[src]*dinv[dst]
// 16 lanes per edge, each lane owns one float4 (64 floats / edge).
// Vector RED (sm_90+) cuts atomic count 4x vs scalar atomicAdd.
// ---------------------------------------------------------------------------
__global__ void k_scatter(const int* __restrict__ src, const int* __restrict__ dst,
                          const float* __restrict__ dinv,
                          const float4* __restrict__ xw, float4* __restrict__ agg, int E) {
    int t = blockIdx.x * blockDim.x + threadIdx.x;
    int e = t >> 4;
    if (e >= E) return;
    int lane = t & 15;
    int s = src[e];
    int d = dst[e];
    float norm = dinv[s] * dinv[d];
    float4 v = __ldg(&xw[s * 16 + lane]);
    v.x *= norm; v.y *= norm; v.z *= norm; v.w *= norm;
    float4* p = const_cast<float4*>(&agg[d * 16 + lane]);
    asm volatile("red.global.add.v4.f32 [%0], {%1, %2, %3, %4};"
                 :: "l"(p), "f"(v.x), "f"(v.y), "f"(v.z), "f"(v.w) : "memory");
}

// ---------------------------------------------------------------------------
// Head: v = relu(agg2 + b2); h = relu(v @ dW1 + db1); out = h @ dW2 + db2
// blockDim = (64, 4). All weights staged in smem.
// ---------------------------------------------------------------------------
__global__ void k_head(const float* __restrict__ agg, const float* __restrict__ b2,
                       const float* __restrict__ dW1, const float* __restrict__ db1,
                       const float* __restrict__ dW2, const float* __restrict__ db2,
                       float* __restrict__ out, int n) {
    __shared__ float sW1[FDIM * FDIM];
    __shared__ float sW2[FDIM * 16];
    __shared__ float sb[FDIM + FDIM + 16];     // b2 | db1 | db2
    __shared__ float v[4][FDIM];
    __shared__ float h[4][FDIM];
    const int tx = threadIdx.x;
    const int ty = threadIdx.y;
    const int tid = ty * 64 + tx;

    #pragma unroll
    for (int i = tid; i < FDIM * FDIM; i += 256) sW1[i] = dW1[i];
    #pragma unroll
    for (int i = tid; i < FDIM * 16; i += 256) sW2[i] = dW2[i];
    if (tid < 64)        sb[tid]       = b2[tid];
    else if (tid < 128)  sb[tid]       = db1[tid - 64];
    else if (tid < 144)  sb[tid]       = db2[tid - 128];

    const int row = blockIdx.x * 4 + ty;
    __syncthreads();

    if (row < n)
        v[ty][tx] = fmaxf(agg[row * FDIM + tx] + sb[tx], 0.0f);
    __syncthreads();

    if (row < n) {
        float a = 0.0f;
        #pragma unroll
        for (int k = 0; k < FDIM; k++)
            a = fmaf(v[ty][k], sW1[k * FDIM + tx], a);
        h[ty][tx] = fmaxf(a + sb[64 + tx], 0.0f);
    }
    __syncthreads();

    if (row < n && tx < 16) {
        float a = 0.0f;
        #pragma unroll
        for (int k = 0; k < FDIM; k++)
            a = fmaf(h[ty][k], sW2[k * 16 + tx], a);
        out[row * 16 + tx] = a + sb[128 + tx];
    }
}

// ---------------------------------------------------------------------------
extern "C" void kernel_launch(void* const* d_in, const int* in_sizes, int n_in,
                              void* d_out, int out_size) {
    const float* x   = (const float*)d_in[0];
    const int*   ei  = (const int*)  d_in[1];
    const float* W1  = (const float*)d_in[2];
    const float* b1  = (const float*)d_in[3];
    const float* W2  = (const float*)d_in[4];
    const float* b2  = (const float*)d_in[5];
    const float* dW1 = (const float*)d_in[6];
    const float* db1 = (const float*)d_in[7];
    const float* dW2 = (const float*)d_in[8];
    const float* db2 = (const float*)d_in[9];
    float* out = (float*)d_out;

    const int N = in_sizes[0] / FDIM;
    const int E = in_sizes[1] / 2;
    const int* src = ei;
    const int* dst = ei + E;

    float* dinv; float* xw; float* agg;
    cudaGetSymbolAddress((void**)&dinv, g_dinv);
    cudaGetSymbolAddress((void**)&xw,  g_xw);
    cudaGetSymbolAddress((void**)&agg, g_agg);

    const int TB = 256;
    dim3 gblk(64, 4);
    const int rowBlocks = (N + 3) / 4;
    const int n16 = N * 16;

    // degrees
    k_deg_init <<<(N + TB - 1) / TB, TB>>>(dinv, N);
    k_deg_count<<<(E + TB - 1) / TB, TB>>>(dst, dinv, E);
    k_deg_rsqrt<<<(N + TB - 1) / TB, TB>>>(dinv, N);

    // layer 1: xw = x @ W1 ; agg = scatter(norm * xw)
    k_gemm64<false><<<rowBlocks, gblk>>>(x, W1, nullptr, xw, N);
    k_self_init<<<(n16 + TB - 1) / TB, TB>>>((const float4*)xw, (float4*)agg, dinv, n16);
    k_scatter<<<((long long)E * 16 + TB - 1) / TB, TB>>>(src, dst, dinv,
                                                         (const float4*)xw, (float4*)agg, E);

    // layer 2: xw = relu(agg + b1) @ W2 ; agg = scatter(norm * xw)
    k_gemm64<true><<<rowBlocks, gblk>>>(agg, W2, b1, xw, N);
    k_self_init<<<(n16 + TB - 1) / TB, TB>>>((const float4*)xw, (float4*)agg, dinv, n16);
    k_scatter<<<((long long)E * 16 + TB - 1) / TB, TB>>>(src, dst, dinv,
                                                         (const float4*)xw, (float4*)agg, E);

    // head MLP (bias+relu of layer 2 fused inside)
    k_head<<<rowBlocks, gblk>>>(agg, b2, dW1, db1, dW2, db2, out, N);
}

// round 3
// speedup vs baseline: 1.5709x; 1.5709x over previous
#include <cuda_runtime.h>
#include <cstdint>

#define NODES_MAX 100000
#define FDIM 64
#define RPB 32            // rows per block
#define CPG 8             // cols per thread (col group width)

// Scratch (allocation-free rule: __device__ globals)
__device__ float g_dinv[NODES_MAX];                // rsqrt(deg)
__device__ float g_xws[NODES_MAX * FDIM];          // (x @ W) * dinv[row]
__device__ float g_agg[NODES_MAX * FDIM];          // scatter accumulator

// ---------------------------------------------------------------------------
// Degree: deg[i] = 1 (self loop) + count(dst == i); then dinv = rsqrt(deg)
// ---------------------------------------------------------------------------
__global__ void k_deg_init(float* deg, int n) {
    int i = blockIdx.x * blockDim.x + threadIdx.x;
    if (i < n) deg[i] = 1.0f;
}
__global__ void k_deg_count(const int* __restrict__ dst, float* deg, int E) {
    int e = blockIdx.x * blockDim.x + threadIdx.x;
    if (e < E) atomicAdd(&deg[dst[e]], 1.0f);
}
__global__ void k_deg_rsqrt(float* deg, int n) {
    int i = blockIdx.x * blockDim.x + threadIdx.x;
    if (i < n) deg[i] = rsqrtf(deg[i]);
}

// ---------------------------------------------------------------------------
// GEMM + GCN epilogue:
//   acc = f(in[row]) @ W          (PRE: f(v)=relu(v + bin))
//   xws[row] = acc * dinv[row]    (pre-scaled by src-side norm)
//   agg[row] = acc * dinv[row]^2  (self-loop contribution, replaces self_init)
// blockDim (32, 8): lane = row-in-block, ty = col group of 8.
// Register tile of 8 outputs/thread; W loads are warp-broadcast LDS.128.
// ---------------------------------------------------------------------------
template<bool PRE>
__global__ void __launch_bounds__(256) k_gemm64(
        const float* __restrict__ in, const float* __restrict__ W,
        const float* __restrict__ bin, const float* __restrict__ dinv,
        float* __restrict__ xws, float* __restrict__ agg, int n) {
    __shared__ float Ws[FDIM * FDIM];
    __shared__ float rb[RPB][FDIM + 1];       // pad -> conflict-free column reads
    const int lane = threadIdx.x;             // 0..31 row in block
    const int cg   = threadIdx.y;             // 0..7  col group
    const int tid  = cg * 32 + lane;
    const int row0 = blockIdx.x * RPB;

    // stage W (4096 floats, 16/thread, vectorized)
    const float4* W4 = (const float4*)W;
    float4* Ws4 = (float4*)Ws;
    #pragma unroll
    for (int i = tid; i < FDIM * FDIM / 4; i += 256) Ws4[i] = W4[i];

    // stage 32 input rows (coalesced), fused bias+relu for layer 2
    #pragma unroll
    for (int i = tid; i < RPB * FDIM; i += 256) {
        int r = i >> 6, c = i & 63;
        int row = row0 + r;
        float v = (row < n) ? in[row * FDIM + c] : 0.0f;
        if (PRE) v = fmaxf(v + bin[c], 0.0f);
        rb[r][c] = v;
    }
    __syncthreads();

    const int row = row0 + lane;
    if (row >= n) return;

    float acc[CPG];
    #pragma unroll
    for (int j = 0; j < CPG; j++) acc[j] = 0.0f;

    #pragma unroll
    for (int k = 0; k < FDIM; k++) {
        float a = rb[lane][k];
        float4 w0 = *(const float4*)&Ws[k * FDIM + cg * CPG];
        float4 w1 = *(const float4*)&Ws[k * FDIM + cg * CPG + 4];
        acc[0] = fmaf(a, w0.x, acc[0]);
        acc[1] = fmaf(a, w0.y, acc[1]);
        acc[2] = fmaf(a, w0.z, acc[2]);
        acc[3] = fmaf(a, w0.w, acc[3]);
        acc[4] = fmaf(a, w1.x, acc[4]);
        acc[5] = fmaf(a, w1.y, acc[5]);
        acc[6] = fmaf(a, w1.z, acc[6]);
        acc[7] = fmaf(a, w1.w, acc[7]);
    }

    const float di = dinv[row];
    float4 s0, s1, a0, a1;
    s0.x = acc[0]*di; s0.y = acc[1]*di; s0.z = acc[2]*di; s0.w = acc[3]*di;
    s1.x = acc[4]*di; s1.y = acc[5]*di; s1.z = acc[6]*di; s1.w = acc[7]*di;
    a0.x = s0.x*di; a0.y = s0.y*di; a0.z = s0.z*di; a0.w = s0.w*di;
    a1.x = s1.x*di; a1.y = s1.y*di; a1.z = s1.z*di; a1.w = s1.w*di;
    float* xp = xws + row * FDIM + cg * CPG;
    float* ap = agg + row * FDIM + cg * CPG;
    *(float4*)(xp)     = s0;
    *(float4*)(xp + 4) = s1;
    *(float4*)(ap)     = a0;
    *(float4*)(ap + 4) = a1;
}

// ---------------------------------------------------------------------------
// Edge scatter: agg[dst,:] += xws[src,:] * dinv[dst]   (xws pre-scaled by src)
// 16 lanes per edge, one float4 each; vector RED.
// ---------------------------------------------------------------------------
__global__ void k_scatter(const int* __restrict__ src, const int* __restrict__ dst,
                          const float* __restrict__ dinv,
                          const float4* __restrict__ xws, float4* __restrict__ agg, int E) {
    int t = blockIdx.x * blockDim.x + threadIdx.x;
    int e = t >> 4;
    if (e >= E) return;
    int lane = t & 15;
    int s = src[e];
    int d = dst[e];
    float nd = dinv[d];
    float4 v = __ldg(&xws[s * 16 + lane]);
    v.x *= nd; v.y *= nd; v.z *= nd; v.w *= nd;
    float4* p = &agg[d * 16 + lane];
    asm volatile("red.global.add.v4.f32 [%0], {%1, %2, %3, %4};"
                 :: "l"(p), "f"(v.x), "f"(v.y), "f"(v.z), "f"(v.w) : "memory");
}

// ---------------------------------------------------------------------------
// Head: v = relu(agg + b2); h = relu(v @ dW1 + db1); out = h @ dW2 + db2
// Same register-tiled structure as k_gemm64.
// ---------------------------------------------------------------------------
__global__ void __launch_bounds__(256) k_head(
        const float* __restrict__ agg, const float* __restrict__ b2,
        const float* __restrict__ dW1, const float* __restrict__ db1,
        const float* __restrict__ dW2, const float* __restrict__ db2,
        float* __restrict__ out, int n) {
    __shared__ float sW1[FDIM * FDIM];
    __shared__ float sW2[FDIM * 16];
    __shared__ float sb[2 * FDIM + 16];        // b2 | db1 | db2
    __shared__ float vb[RPB][FDIM + 1];
    __shared__ float hb[RPB][FDIM + 1];
    const int lane = threadIdx.x;
    const int cg   = threadIdx.y;
    const int tid  = cg * 32 + lane;
    const int row0 = blockIdx.x * RPB;

    {
        const float4* a4 = (const float4*)dW1;
        float4* s4 = (float4*)sW1;
        #pragma unroll
        for (int i = tid; i < FDIM * FDIM / 4; i += 256) s4[i] = a4[i];
        const float4* b4 = (const float4*)dW2;
        float4* t4 = (float4*)sW2;
        if (tid < FDIM * 16 / 4) t4[tid] = b4[tid];
        if (tid < 64)        sb[tid] = b2[tid];
        else if (tid < 128)  sb[tid] = db1[tid - 64];
        else if (tid < 144)  sb[tid] = db2[tid - 128];
    }

    // v = relu(agg + b2)
    #pragma unroll
    for (int i = tid; i < RPB * FDIM; i += 256) {
        int r = i >> 6, c = i & 63;
        int row = row0 + r;
        float x = (row < n) ? agg[row * FDIM + c] : 0.0f;
        vb[r][c] = fmaxf(x + b2[c], 0.0f);
    }
    __syncthreads();

    const int row = row0 + lane;
    const bool ok = row < n;

    // h = relu(v @ dW1 + db1)  -> smem
    if (ok) {
        float acc[CPG];
        #pragma unroll
        for (int j = 0; j < CPG; j++) acc[j] = 0.0f;
        #pragma unroll
        for (int k = 0; k < FDIM; k++) {
            float a = vb[lane][k];
            float4 w0 = *(const float4*)&sW1[k * FDIM + cg * CPG];
            float4 w1 = *(const float4*)&sW1[k * FDIM + cg * CPG + 4];
            acc[0] = fmaf(a, w0.x, acc[0]);
            acc[1] = fmaf(a, w0.y, acc[1]);
            acc[2] = fmaf(a, w0.z, acc[2]);
            acc[3] = fmaf(a, w0.w, acc[3]);
            acc[4] = fmaf(a, w1.x, acc[4]);
            acc[5] = fmaf(a, w1.y, acc[5]);
            acc[6] = fmaf(a, w1.z, acc[6]);
            acc[7] = fmaf(a, w1.w, acc[7]);
        }
        #pragma unroll
        for (int j = 0; j < CPG; j++)
            hb[lane][cg * CPG + j] = fmaxf(acc[j] + sb[64 + cg * CPG + j], 0.0f);
    }
    __syncthreads();

    // out = h @ dW2 + db2  (16 cols: 2 per thread)
    if (ok) {
        float o0 = 0.0f, o1 = 0.0f;
        #pragma unroll
        for (int k = 0; k < FDIM; k++) {
            float a = hb[lane][k];
            float2 w = *(const float2*)&sW2[k * 16 + cg * 2];
            o0 = fmaf(a, w.x, o0);
            o1 = fmaf(a, w.y, o1);
        }
        float2 o;
        o.x = o0 + sb[128 + cg * 2];
        o.y = o1 + sb[128 + cg * 2 + 1];
        *(float2*)&out[row * 16 + cg * 2] = o;
    }
}

// ---------------------------------------------------------------------------
extern "C" void kernel_launch(void* const* d_in, const int* in_sizes, int n_in,
                              void* d_out, int out_size) {
    const float* x   = (const float*)d_in[0];
    const int*   ei  = (const int*)  d_in[1];
    const float* W1  = (const float*)d_in[2];
    const float* b1  = (const float*)d_in[3];
    const float* W2  = (const float*)d_in[4];
    const float* b2  = (const float*)d_in[5];
    const float* dW1 = (const float*)d_in[6];
    const float* db1 = (const float*)d_in[7];
    const float* dW2 = (const float*)d_in[8];
    const float* db2 = (const float*)d_in[9];
    float* out = (float*)d_out;

    const int N = in_sizes[0] / FDIM;
    const int E = in_sizes[1] / 2;
    const int* src = ei;
    const int* dst = ei + E;

    float* dinv; float* xws; float* agg;
    cudaGetSymbolAddress((void**)&dinv, g_dinv);
    cudaGetSymbolAddress((void**)&xws, g_xws);
    cudaGetSymbolAddress((void**)&agg, g_agg);

    const int TB = 256;
    dim3 gblk(32, 8);
    const int rowBlocks = (N + RPB - 1) / RPB;

    // degrees
    k_deg_init <<<(N + TB - 1) / TB, TB>>>(dinv, N);
    k_deg_count<<<(E + TB - 1) / TB, TB>>>(dst, dinv, E);
    k_deg_rsqrt<<<(N + TB - 1) / TB, TB>>>(dinv, N);

    // layer 1
    k_gemm64<false><<<rowBlocks, gblk>>>(x, W1, nullptr, dinv, xws, agg, N);
    k_scatter<<<((long long)E * 16 + TB - 1) / TB, TB>>>(src, dst, dinv,
                                                         (const float4*)xws, (float4*)agg, E);
    // layer 2 (bias+relu of layer 1 fused into input stage)
    k_gemm64<true><<<rowBlocks, gblk>>>(agg, W2, b1, dinv, xws, agg, N);
    k_scatter<<<((long long)E * 16 + TB - 1) / TB, TB>>>(src, dst, dinv,
                                                         (const float4*)xws, (float4*)agg, E);

    // head MLP
    k_head<<<rowBlocks, gblk>>>(agg, b2, dW1, db1, dW2, db2, out, N);
}